// round 6
// baseline (speedup 1.0000x reference)
#include <cuda_runtime.h>
#include <cstdint>

#define NB   32    // num 4x4 blocks
#define BS   4
#define DIM  128   // NB*BS
#define NREL 16    // edge relations (blocks[16] = self-loop)

// Per-relation bins for directed-edge records. Capacity = 2*E (all edges one
// relation) with slack. Record: {src | dst<<16, weight_bits}.
#define BIN_CAP 327680
__device__ int2 g_rec[NREL][BIN_CAP];   // ~42 MB static scratch
__device__ int  g_cursor[NREL];

// ---------------------------------------------------------------------------
// Self-loop kernel: one warp per node, lane b handles block b.
// Also initializes d_out (poisoned) and zeros the bin cursors (it is the
// first launch in the stream, so ordering vs scatter is guaranteed).
// ---------------------------------------------------------------------------
__global__ __launch_bounds__(256) void self_kernel(
    const float* __restrict__ x,
    const int*   __restrict__ mask,
    const float* __restrict__ blocks,
    float* __restrict__ out,
    int n_nodes)
{
    if (blockIdx.x == 0 && threadIdx.x < NREL)
        g_cursor[threadIdx.x] = 0;

    int gw   = (blockIdx.x * blockDim.x + threadIdx.x) >> 5;
    int lane = threadIdx.x & 31;
    if (gw >= n_nodes) return;
    const int n = gw;

    float4 o = make_float4(0.f, 0.f, 0.f, 0.f);
    if (__ldg(mask + n) != 0) {
        float4 xi = __ldg((const float4*)(x + (size_t)n * DIM) + lane);
        const float4* W = (const float4*)blocks + ((size_t)NREL * NB + lane) * 4;
        float4 w0 = __ldg(W + 0);
        float4 w1 = __ldg(W + 1);
        float4 w2 = __ldg(W + 2);
        float4 w3 = __ldg(W + 3);
        o.x = xi.x * w0.x + xi.y * w1.x + xi.z * w2.x + xi.w * w3.x;
        o.y = xi.x * w0.y + xi.y * w1.y + xi.z * w2.y + xi.w * w3.y;
        o.z = xi.x * w0.z + xi.y * w1.z + xi.z * w2.z + xi.w * w3.z;
        o.w = xi.x * w0.w + xi.y * w1.w + xi.z * w2.w + xi.w * w3.w;
    }
    *((float4*)(out + (size_t)n * DIM) + lane) = o;
}

// ---------------------------------------------------------------------------
// Scatter kernel: bin both directed versions of each edge by relation.
// 16 hot L2 cursors; ATOMG under contention ~= REDG throughput.
// ---------------------------------------------------------------------------
__global__ __launch_bounds__(256) void scatter_kernel(
    const int*   __restrict__ src,
    const int*   __restrict__ tgt,
    const int*   __restrict__ et,
    const float* __restrict__ ew,
    int n_edges)
{
    int stride = gridDim.x * blockDim.x;
    for (int e = blockIdx.x * blockDim.x + threadIdx.x; e < n_edges; e += stride) {
        const int   s = __ldg(src + e);
        const int   t = __ldg(tgt + e);
        const int   r = __ldg(et + e);
        const int   w = __float_as_int(__ldg(ew + e));
        int pos = atomicAdd(&g_cursor[r], 2);
        if (pos + 1 < BIN_CAP) {
            g_rec[r][pos]     = make_int2(s | (t << 16), w);
            g_rec[r][pos + 1] = make_int2(t | (s << 16), w);
        }
    }
}

// ---------------------------------------------------------------------------
// Consume kernel: warps take 32-edge chunks inside one relation bin, so the
// relation is uniform per chunk -> W held in 16 registers per lane, loaded
// once per chunk. Per edge: coalesced x gather (LDG.128) + red.global.v4.
// ---------------------------------------------------------------------------
#define CONS_THREADS 256
#define CONS_CTAS    1184   // 8/SM attempted; grid-stride handles the rest

__global__ __launch_bounds__(CONS_THREADS) void consume_kernel(
    const float* __restrict__ x,
    const float* __restrict__ blocks,
    float* __restrict__ out)
{
    const int lane = threadIdx.x & 31;
    const int warp = (blockIdx.x * CONS_THREADS + threadIdx.x) >> 5;
    const int nw   = (gridDim.x * CONS_THREADS) >> 5;

    for (int r = 0; r < NREL; r++) {
        const int cnt = g_cursor[r];          // L2-hot scalar
        const int nch = (cnt + 31) >> 5;

        for (int c = warp; c < nch; c += nw) {
            // W for relation r, this lane's block (once per 32 edges)
            const float4* Wp = (const float4*)blocks + ((size_t)r * NB + lane) * 4;
            float4 w0 = __ldg(Wp + 0);
            float4 w1 = __ldg(Wp + 1);
            float4 w2 = __ldg(Wp + 2);
            float4 w3 = __ldg(Wp + 3);

            const int base = c << 5;
            const int cc   = min(32, cnt - base);

            int2 rec = make_int2(0, 0);
            if (lane < cc) rec = __ldg(&g_rec[r][base + lane]);

            for (int k = 0; k < cc; k++) {
                const int   st = __shfl_sync(0xffffffffu, rec.x, k);
                const float w  = __shfl_sync(0xffffffffu, __int_as_float(rec.y), k);
                const int s = st & 0xFFFF;
                const int t = st >> 16;

                float4 xi = __ldg((const float4*)(x + (size_t)s * DIM) + lane);

                float4 o;
                o.x = (xi.x * w0.x + xi.y * w1.x + xi.z * w2.x + xi.w * w3.x) * w;
                o.y = (xi.x * w0.y + xi.y * w1.y + xi.z * w2.y + xi.w * w3.y) * w;
                o.z = (xi.x * w0.z + xi.y * w1.z + xi.z * w2.z + xi.w * w3.z) * w;
                o.w = (xi.x * w0.w + xi.y * w1.w + xi.z * w2.w + xi.w * w3.w) * w;

                float* dst = out + (size_t)t * DIM + lane * 4;   // 16B aligned
                asm volatile("red.global.add.v4.f32 [%0], {%1, %2, %3, %4};"
                             :: "l"(dst), "f"(o.x), "f"(o.y), "f"(o.z), "f"(o.w));
            }
        }
    }
}

// ---------------------------------------------------------------------------
// Inputs (metadata order):
//   0: x              float32 (10000*128)
//   1: node_keep_mask int32   (10000)
//   2: source         int32   (160000)
//   3: target         int32   (160000)
//   4: edge_type      int32   (160000)
//   5: edge_weights   float32 (160000)
//   6: blocks         float32 (17*32*4*4)
// Output: float32 (10000*128)
// ---------------------------------------------------------------------------
extern "C" void kernel_launch(void* const* d_in, const int* in_sizes, int n_in,
                              void* d_out, int out_size)
{
    const float* x      = (const float*)d_in[0];
    const int*   mask   = (const int*)d_in[1];
    const int*   src    = (const int*)d_in[2];
    const int*   tgt    = (const int*)d_in[3];
    const int*   et     = (const int*)d_in[4];
    const float* ew     = (const float*)d_in[5];
    const float* blocks = (const float*)d_in[6];
    float*       out    = (float*)d_out;

    const int n_nodes = in_sizes[1];
    const int n_edges = in_sizes[2];

    // 1) Self-loop + out init + cursor zeroing (first in stream)
    {
        int threads = 256;
        int blocks_ = (n_nodes * 32 + threads - 1) / threads;
        self_kernel<<<blocks_, threads>>>(x, mask, blocks, out, n_nodes);
    }

    // 2) Bin directed edges by relation
    {
        int threads = 256;
        int blocks_ = min(1184, (n_edges + threads - 1) / threads);
        scatter_kernel<<<blocks_, threads>>>(src, tgt, et, ew, n_edges);
    }

    // 3) Relation-uniform message passing
    consume_kernel<<<CONS_CTAS, CONS_THREADS>>>(x, blocks, out);
}

// round 7
// speedup vs baseline: 3.0198x; 3.0198x over previous
#include <cuda_runtime.h>
#include <cstdint>

#define NB   32    // num 4x4 blocks
#define BS   4
#define DIM  128   // NB*BS
#define NREL 16    // edge relations (blocks[16] = self-loop)

// ---------------------------------------------------------------------------
// Self-loop kernel: grid-stride, warp-per-node, lane b = block b.
// W (relation 16) register-resident, loaded once per warp.
// Also initializes d_out (poisoned). mask is bool serialized as int32.
// ---------------------------------------------------------------------------
__global__ __launch_bounds__(256) void self_kernel(
    const float* __restrict__ x,
    const int*   __restrict__ mask,
    const float* __restrict__ blocks,
    float* __restrict__ out,
    int n_nodes)
{
    const int lane = threadIdx.x & 31;
    const int warp = (blockIdx.x * blockDim.x + threadIdx.x) >> 5;
    const int nw   = (gridDim.x * blockDim.x) >> 5;

    const float4* Wp = (const float4*)blocks + ((size_t)NREL * NB + lane) * 4;
    const float4 w0 = __ldg(Wp + 0);
    const float4 w1 = __ldg(Wp + 1);
    const float4 w2 = __ldg(Wp + 2);
    const float4 w3 = __ldg(Wp + 3);

    for (int n = warp; n < n_nodes; n += nw) {
        float4 o = make_float4(0.f, 0.f, 0.f, 0.f);
        if (__ldg(mask + n) != 0) {
            float4 xi = __ldg((const float4*)(x + (size_t)n * DIM) + lane);
            o.x = xi.x * w0.x + xi.y * w1.x + xi.z * w2.x + xi.w * w3.x;
            o.y = xi.x * w0.y + xi.y * w1.y + xi.z * w2.y + xi.w * w3.y;
            o.z = xi.x * w0.z + xi.y * w1.z + xi.z * w2.z + xi.w * w3.z;
            o.w = xi.x * w0.w + xi.y * w1.w + xi.z * w2.w + xi.w * w3.w;
        }
        *((float4*)(out + (size_t)n * DIM) + lane) = o;
    }
}

// ---------------------------------------------------------------------------
// Edge kernel: relation-specialized CTAs. blockIdx.y = relation g.
// Each warp holds relation g's 4x4 block (lane=block) in 16 registers.
// Warps scan 32-edge chunks of the 2E directed-edge list: coalesced et load,
// ballot for et==g, process matching edges via shfl broadcast:
//   coalesced x[src] gather (LDG.128) -> 4x4 GEMV -> red.global.add.v4.f32.
// No atomic cursors, no scratch, deterministic.
// ---------------------------------------------------------------------------
#define EDGE_THREADS 256
#define EDGE_G       37    // CTAs per relation group: 37*16 = 592 CTAs (4/SM)

__global__ __launch_bounds__(EDGE_THREADS) void edge_kernel(
    const float* __restrict__ x,
    const int*   __restrict__ src,
    const int*   __restrict__ tgt,
    const int*   __restrict__ et,
    const float* __restrict__ ew,
    const float* __restrict__ blocks,
    float* __restrict__ out,
    int n_edges)
{
    const int g    = blockIdx.y;            // this CTA's relation
    const int lane = threadIdx.x & 31;

    // Register-resident W for relation g, block = lane (once per warp)
    const float4* Wp = (const float4*)blocks + ((size_t)g * NB + lane) * 4;
    const float4 w0 = __ldg(Wp + 0);
    const float4 w1 = __ldg(Wp + 1);
    const float4 w2 = __ldg(Wp + 2);
    const float4 w3 = __ldg(Wp + 3);

    const int warp = (blockIdx.x * EDGE_THREADS + threadIdx.x) >> 5;
    const int nw   = (gridDim.x * EDGE_THREADS) >> 5;
    const int E2   = 2 * n_edges;
    const int nch  = (E2 + 31) >> 5;

    for (int c = warp; c < nch; c += nw) {
        const int d     = (c << 5) + lane;
        const bool valid = (d < E2);
        const bool fwd   = (d < n_edges);
        const int  e     = fwd ? d : d - n_edges;

        int r = -1;
        if (valid) r = __ldg(et + e);

        unsigned m = __ballot_sync(0xffffffffu, r == g);
        if (m == 0u) continue;

        // Only matching lanes fetch the rest of their edge's metadata
        int   s_l = 0, t_l = 0;
        float w_l = 0.f;
        if (r == g) {
            s_l = __ldg(fwd ? src + e : tgt + e);
            t_l = __ldg(fwd ? tgt + e : src + e);
            w_l = __ldg(ew + e);
        }

        while (m) {
            const int k = __ffs(m) - 1;
            m &= m - 1;
            const int   s = __shfl_sync(0xffffffffu, s_l, k);
            const int   t = __shfl_sync(0xffffffffu, t_l, k);
            const float w = __shfl_sync(0xffffffffu, w_l, k);

            float4 xi = __ldg((const float4*)(x + (size_t)s * DIM) + lane);

            float4 o;
            o.x = (xi.x * w0.x + xi.y * w1.x + xi.z * w2.x + xi.w * w3.x) * w;
            o.y = (xi.x * w0.y + xi.y * w1.y + xi.z * w2.y + xi.w * w3.y) * w;
            o.z = (xi.x * w0.z + xi.y * w1.z + xi.z * w2.z + xi.w * w3.z) * w;
            o.w = (xi.x * w0.w + xi.y * w1.w + xi.z * w2.w + xi.w * w3.w) * w;

            float* dst = out + (size_t)t * DIM + lane * 4;   // 16B aligned
            asm volatile("red.global.add.v4.f32 [%0], {%1, %2, %3, %4};"
                         :: "l"(dst), "f"(o.x), "f"(o.y), "f"(o.z), "f"(o.w));
        }
    }
}

// ---------------------------------------------------------------------------
// Inputs (metadata order):
//   0: x              float32 (10000*128)
//   1: node_keep_mask int32   (10000)
//   2: source         int32   (160000)
//   3: target         int32   (160000)
//   4: edge_type      int32   (160000)
//   5: edge_weights   float32 (160000)
//   6: blocks         float32 (17*32*4*4)
// Output: float32 (10000*128)
// ---------------------------------------------------------------------------
extern "C" void kernel_launch(void* const* d_in, const int* in_sizes, int n_in,
                              void* d_out, int out_size)
{
    const float* x      = (const float*)d_in[0];
    const int*   mask   = (const int*)d_in[1];
    const int*   src    = (const int*)d_in[2];
    const int*   tgt    = (const int*)d_in[3];
    const int*   et     = (const int*)d_in[4];
    const float* ew     = (const float*)d_in[5];
    const float* blocks = (const float*)d_in[6];
    float*       out    = (float*)d_out;

    const int n_nodes = in_sizes[1];
    const int n_edges = in_sizes[2];

    // 1) Self-loop + out init (serial before edge REDs via stream order)
    self_kernel<<<296, 256>>>(x, mask, blocks, out, n_nodes);

    // 2) Relation-specialized edge messages
    dim3 grid(EDGE_G, NREL);
    edge_kernel<<<grid, EDGE_THREADS>>>(x, src, tgt, et, ew, blocks, out, n_edges);
}